// round 2
// baseline (speedup 1.0000x reference)
#include <cuda_runtime.h>
#include <cuda_bf16.h>

// FCGAT collapses algebraically:
//   out = relu(x @ W_w^T + W_b)
// because einsum('nkj,nkd->nkd', softmax(e, axis=2), h) = h * sum_j a = h * 1.
// Residual problem: GEMM C[M=32768, 256] = A[M,256] * W[256,256]^T + bias, relu.
//
// Round 1: fp32 shared-memory tiled GEMM (correctness baseline for the
// simplification + rel_err headroom measurement for tensor-core rounds).

#define D_DIM 256
#define BM 64
#define BN 64
#define BK 32
#define TM 4
#define TN 4
#define PAD 4   // keep rows 16B-aligned for LDS.128 while shifting banks

__global__ __launch_bounds__(256, 2)
void fcgat_gemm_relu(const float* __restrict__ A,
                     const float* __restrict__ W,
                     const float* __restrict__ bias,
                     float* __restrict__ C)
{
    __shared__ float As[BK][BM + PAD];
    __shared__ float Bs[BK][BN + PAD];

    const int t  = threadIdx.x;
    const int tx = t & 15;        // N direction (16 threads)
    const int ty = t >> 4;        // M direction (16 threads)

    const float* Ablk = A + (size_t)blockIdx.y * BM * D_DIM;
    const float* Wblk = W + (size_t)blockIdx.x * BN * D_DIM;

    float acc[TM][TN];
    #pragma unroll
    for (int i = 0; i < TM; i++)
        #pragma unroll
        for (int j = 0; j < TN; j++)
            acc[i][j] = 0.0f;

    for (int k0 = 0; k0 < D_DIM; k0 += BK) {
        // Load tiles: 64 rows x 32 cols each = 512 float4; 256 threads x 2.
        #pragma unroll
        for (int i = 0; i < 2; i++) {
            int idx = t + i * 256;
            int row = idx >> 3;            // 0..63
            int kc  = (idx & 7) * 4;       // 0..28
            float4 va = *(const float4*)(Ablk + (size_t)row * D_DIM + k0 + kc);
            As[kc + 0][row] = va.x;
            As[kc + 1][row] = va.y;
            As[kc + 2][row] = va.z;
            As[kc + 3][row] = va.w;
            float4 vb = *(const float4*)(Wblk + (size_t)row * D_DIM + k0 + kc);
            Bs[kc + 0][row] = vb.x;
            Bs[kc + 1][row] = vb.y;
            Bs[kc + 2][row] = vb.z;
            Bs[kc + 3][row] = vb.w;
        }
        __syncthreads();

        #pragma unroll
        for (int kk = 0; kk < BK; kk++) {
            float4 a = *(const float4*)&As[kk][ty * TM];
            float4 b = *(const float4*)&Bs[kk][tx * TN];
            float av[TM] = {a.x, a.y, a.z, a.w};
            float bv[TN] = {b.x, b.y, b.z, b.w};
            #pragma unroll
            for (int i = 0; i < TM; i++)
                #pragma unroll
                for (int j = 0; j < TN; j++)
                    acc[i][j] = fmaf(av[i], bv[j], acc[i][j]);
        }
        __syncthreads();
    }

    // Epilogue: bias + relu, float4 stores.
    const int ncol = blockIdx.x * BN + tx * TN;
    float4 bv = *(const float4*)(bias + ncol);
    #pragma unroll
    for (int i = 0; i < TM; i++) {
        size_t mrow = (size_t)blockIdx.y * BM + ty * TM + i;
        float4 o;
        o.x = fmaxf(acc[i][0] + bv.x, 0.0f);
        o.y = fmaxf(acc[i][1] + bv.y, 0.0f);
        o.z = fmaxf(acc[i][2] + bv.z, 0.0f);
        o.w = fmaxf(acc[i][3] + bv.w, 0.0f);
        *(float4*)(C + mrow * D_DIM + ncol) = o;
    }
}

extern "C" void kernel_launch(void* const* d_in, const int* in_sizes, int n_in,
                              void* d_out, int out_size)
{
    const float* x    = (const float*)d_in[0];  // [N, K, D] = [64, 512, 256]
    const float* W_w  = (const float*)d_in[1];  // [256, 256]
    const float* W_b  = (const float*)d_in[2];  // [256]
    // d_in[3] (att_w) and d_in[4] (att_b) are mathematically irrelevant:
    // softmax rows sum to 1, so the 'nkj,nkd->nkd' einsum is identity on h.
    float* out = (float*)d_out;

    int M = in_sizes[0] / D_DIM;                // 32768
    dim3 grid(D_DIM / BN, M / BM);              // (4, 512)
    fcgat_gemm_relu<<<grid, 256>>>(x, W_w, W_b, out);
}

// round 4
// speedup vs baseline: 2.7886x; 2.7886x over previous
#include <cuda_runtime.h>
#include <cuda_bf16.h>
#include <cstdint>

// out = relu(x @ W_w^T + W_b)   (attention collapses: softmax rows sum to 1,
// validated R2 at rel_err 5.9e-8).
//
// R4: tcgen05 is NOT emittable (bench PTX targets compute_103, no 'a' features).
// Use the stable-ISA tensor path: ldmatrix + mma.sync.m16n8k16 bf16 with
// split-precision compensation:
//   x = xh + xl (both bf16);  h ≈ xh*Wh + xh*Wl + xl*Wh   (drop xl*Wl ~ 2^-16)
//
// CTA: 128(M) x 64(N), BK=32, 256 threads (8 warps, 4x2), warp tile 32x32.

#define D_DIM 256
#define BM 128
#define BN 64
#define BK 32
#define N_CHUNKS (D_DIM / BK)      // 8
#define ROWB 80                    // smem row stride bytes: (32+8) bf16 -> conflict-free ldmatrix

// smem byte offsets (static buffer)
#define OFF_AH 0
#define OFF_AL (OFF_AH + BM * ROWB)    // 10240
#define OFF_BH (OFF_AL + BM * ROWB)    // 20480
#define OFF_BL (OFF_BH + BN * ROWB)    // 25600
#define SMEM_BYTES (OFF_BL + BN * ROWB) // 30720

__device__ __forceinline__ uint32_t smem_u32(const void* p) {
    uint32_t a;
    asm("{ .reg .u64 t; cvta.to.shared.u64 t, %1; cvt.u32.u64 %0, t; }" : "=r"(a) : "l"(p));
    return a;
}

__device__ __forceinline__ void ldsm_x4(uint32_t* r, uint32_t addr) {
    asm volatile("ldmatrix.sync.aligned.m8n8.x4.shared.b16 {%0,%1,%2,%3}, [%4];"
                 : "=r"(r[0]), "=r"(r[1]), "=r"(r[2]), "=r"(r[3]) : "r"(addr));
}

__device__ __forceinline__ void mma_bf16(float* d, const uint32_t* a, const uint32_t* b) {
    asm volatile("mma.sync.aligned.m16n8k16.row.col.f32.bf16.bf16.f32 "
                 "{%0,%1,%2,%3}, {%4,%5,%6,%7}, {%8,%9}, {%0,%1,%2,%3};"
                 : "+f"(d[0]), "+f"(d[1]), "+f"(d[2]), "+f"(d[3])
                 : "r"(a[0]), "r"(a[1]), "r"(a[2]), "r"(a[3]),
                   "r"(b[0]), "r"(b[1]));
}

// Split a float4 into bf16 hi + bf16 residual lo, store 8B each.
__device__ __forceinline__ void split_store(unsigned char* smem, uint32_t hi_off,
                                            uint32_t lo_off, float4 v) {
    __nv_bfloat162 h0 = __floats2bfloat162_rn(v.x, v.y);
    __nv_bfloat162 h1 = __floats2bfloat162_rn(v.z, v.w);
    float2 f0 = __bfloat1622float2(h0);
    float2 f1 = __bfloat1622float2(h1);
    __nv_bfloat162 l0 = __floats2bfloat162_rn(v.x - f0.x, v.y - f0.y);
    __nv_bfloat162 l1 = __floats2bfloat162_rn(v.z - f1.x, v.w - f1.y);
    uint2 hv = make_uint2(*(uint32_t*)&h0, *(uint32_t*)&h1);
    uint2 lv = make_uint2(*(uint32_t*)&l0, *(uint32_t*)&l1);
    *(uint2*)(smem + hi_off) = hv;
    *(uint2*)(smem + lo_off) = lv;
}

__global__ __launch_bounds__(256, 2)
void fcgat_hmma(const float* __restrict__ A,     // x  [32768, 256]
                const float* __restrict__ W,     // W  [256, 256]
                const float* __restrict__ bias,  // [256]
                float* __restrict__ C)           // [32768, 256]
{
    __shared__ __align__(16) unsigned char smem[SMEM_BYTES];
    const uint32_t sb = smem_u32(smem);

    const int t   = threadIdx.x;
    const int l   = t & 31;
    const int wid = t >> 5;
    const int wm  = wid & 3;          // 4 warps along M
    const int wn  = wid >> 2;         // 2 warps along N
    const int m0  = wm * 32;
    const int n0  = wn * 32;

    const float* Ag = A + (size_t)blockIdx.y * BM * D_DIM;
    const float* Bg = W + (size_t)blockIdx.x * BN * D_DIM;

    float acc[2][4][4];
    #pragma unroll
    for (int i = 0; i < 2; i++)
        #pragma unroll
        for (int j = 0; j < 4; j++)
            #pragma unroll
            for (int c = 0; c < 4; c++)
                acc[i][j][c] = 0.0f;

    // ldmatrix lane address components (byte offsets within a tile)
    const uint32_t a_lane = (uint32_t)((m0 + (l & 15)) * ROWB + (l >> 4) * 16);
    const uint32_t b_lane = (uint32_t)((n0 + (l & 7) + ((l >> 4) << 3)) * ROWB
                                       + ((l >> 3) & 1) * 16);

    for (int ch = 0; ch < N_CHUNKS; ch++) {
        const int kc = ch * BK;

        // ---- load + split-convert tiles into smem ----
        // A: 128 rows x 8 float4 = 1024 -> 4/thread. B: 64 rows x 8 = 512 -> 2/thread.
        #pragma unroll
        for (int i = 0; i < 4; i++) {
            int idx = t + i * 256;
            int row = idx >> 3;
            int c4  = idx & 7;
            float4 v = *(const float4*)(Ag + (size_t)row * D_DIM + kc + c4 * 4);
            uint32_t so = (uint32_t)(row * ROWB + c4 * 8);
            split_store(smem, OFF_AH + so, OFF_AL + so, v);
        }
        #pragma unroll
        for (int i = 0; i < 2; i++) {
            int idx = t + i * 256;
            int row = idx >> 3;
            int c4  = idx & 7;
            float4 v = *(const float4*)(Bg + (size_t)row * D_DIM + kc + c4 * 4);
            uint32_t so = (uint32_t)(row * ROWB + c4 * 8);
            split_store(smem, OFF_BH + so, OFF_BL + so, v);
        }
        __syncthreads();

        // ---- compute: 2 k16 steps, 3 split products each ----
        #pragma unroll
        for (int ks = 0; ks < 2; ks++) {
            const uint32_t ko = (uint32_t)(ks * 32);   // 16 bf16 = 32 bytes

            uint32_t ah[2][4], al[2][4], bh[2][4], bl[2][4];
            #pragma unroll
            for (int i = 0; i < 2; i++) {
                ldsm_x4(ah[i], sb + OFF_AH + a_lane + ko + i * 16 * ROWB);
                ldsm_x4(al[i], sb + OFF_AL + a_lane + ko + i * 16 * ROWB);
            }
            #pragma unroll
            for (int jp = 0; jp < 2; jp++) {
                ldsm_x4(bh[jp], sb + OFF_BH + b_lane + ko + jp * 16 * ROWB);
                ldsm_x4(bl[jp], sb + OFF_BL + b_lane + ko + jp * 16 * ROWB);
            }

            #pragma unroll
            for (int i = 0; i < 2; i++)
                #pragma unroll
                for (int j = 0; j < 4; j++) {
                    const uint32_t* bhf = bh[j >> 1] + (j & 1) * 2;
                    const uint32_t* blf = bl[j >> 1] + (j & 1) * 2;
                    mma_bf16(acc[i][j], ah[i], bhf);   // xh * Wh
                    mma_bf16(acc[i][j], ah[i], blf);   // xh * Wl
                    mma_bf16(acc[i][j], al[i], bhf);   // xl * Wh
                }
        }
        __syncthreads();
    }

    // ---- epilogue: bias + relu ----
    const int g  = l >> 2;
    const int tc = l & 3;
    #pragma unroll
    for (int i = 0; i < 2; i++) {
        const size_t r0 = (size_t)blockIdx.y * BM + m0 + 16 * i + g;
        const size_t r1 = r0 + 8;
        #pragma unroll
        for (int j = 0; j < 4; j++) {
            const int col = blockIdx.x * BN + n0 + 8 * j + 2 * tc;
            float2 bv = *(const float2*)(bias + col);
            float2 o0, o1;
            o0.x = fmaxf(acc[i][j][0] + bv.x, 0.0f);
            o0.y = fmaxf(acc[i][j][1] + bv.y, 0.0f);
            o1.x = fmaxf(acc[i][j][2] + bv.x, 0.0f);
            o1.y = fmaxf(acc[i][j][3] + bv.y, 0.0f);
            *(float2*)(C + r0 * D_DIM + col) = o0;
            *(float2*)(C + r1 * D_DIM + col) = o1;
        }
    }
}

extern "C" void kernel_launch(void* const* d_in, const int* in_sizes, int n_in,
                              void* d_out, int out_size)
{
    const float* x   = (const float*)d_in[0];
    const float* W_w = (const float*)d_in[1];
    const float* W_b = (const float*)d_in[2];
    float* out = (float*)d_out;

    int M = in_sizes[0] / D_DIM;                  // 32768
    dim3 grid(D_DIM / BN, M / BM);                // (4, 256) = 1024 CTAs
    fcgat_hmma<<<grid, 256>>>(x, W_w, W_b, out);
}

// round 5
// speedup vs baseline: 2.9297x; 1.0506x over previous
#include <cuda_runtime.h>
#include <cuda_bf16.h>
#include <cstdint>

// out = relu(x @ W_w^T + W_b)   (attention collapses: softmax rows sum to 1,
// validated R2 at rel_err 5.9e-8; R4 HMMA split-bf16 at 4.5e-6).
//
// R5: software-pipelined double buffering. Per chunk: issue next chunk's LDGs,
// compute current chunk (LDSM+MMA) — hiding LDG latency behind the tensor pipe —
// then split-convert+STS into the other stage, ONE __syncthreads. This removes
// the exposed gmem latency + one barrier per chunk that bounded R4 (issue=26%).

#define D_DIM 256
#define BM 128
#define BN 64
#define BK 32
#define N_CHUNKS (D_DIM / BK)      // 8
#define ROWB 80                    // smem row stride: (32+8) bf16 -> conflict-free ldmatrix

#define OFF_AH 0
#define OFF_AL (OFF_AH + BM * ROWB)     // 10240
#define OFF_BH (OFF_AL + BM * ROWB)     // 20480
#define OFF_BL (OFF_BH + BN * ROWB)     // 25600
#define STAGE_BYTES (OFF_BL + BN * ROWB) // 30720
#define SMEM_TOTAL (2 * STAGE_BYTES)     // 61440

__device__ __forceinline__ uint32_t smem_u32(const void* p) {
    uint32_t a;
    asm("{ .reg .u64 t; cvta.to.shared.u64 t, %1; cvt.u32.u64 %0, t; }" : "=r"(a) : "l"(p));
    return a;
}

__device__ __forceinline__ void ldsm_x4(uint32_t* r, uint32_t addr) {
    asm volatile("ldmatrix.sync.aligned.m8n8.x4.shared.b16 {%0,%1,%2,%3}, [%4];"
                 : "=r"(r[0]), "=r"(r[1]), "=r"(r[2]), "=r"(r[3]) : "r"(addr));
}

__device__ __forceinline__ void mma_bf16(float* d, const uint32_t* a, const uint32_t* b) {
    asm volatile("mma.sync.aligned.m16n8k16.row.col.f32.bf16.bf16.f32 "
                 "{%0,%1,%2,%3}, {%4,%5,%6,%7}, {%8,%9}, {%0,%1,%2,%3};"
                 : "+f"(d[0]), "+f"(d[1]), "+f"(d[2]), "+f"(d[3])
                 : "r"(a[0]), "r"(a[1]), "r"(a[2]), "r"(a[3]),
                   "r"(b[0]), "r"(b[1]));
}

// Split a float4 into bf16 hi + bf16 residual lo, store 8B each.
__device__ __forceinline__ void split_store(uint32_t sb, uint32_t hi_off,
                                            uint32_t lo_off, float4 v) {
    __nv_bfloat162 h0 = __floats2bfloat162_rn(v.x, v.y);
    __nv_bfloat162 h1 = __floats2bfloat162_rn(v.z, v.w);
    float2 f0 = __bfloat1622float2(h0);
    float2 f1 = __bfloat1622float2(h1);
    __nv_bfloat162 l0 = __floats2bfloat162_rn(v.x - f0.x, v.y - f0.y);
    __nv_bfloat162 l1 = __floats2bfloat162_rn(v.z - f1.x, v.w - f1.y);
    uint32_t h0u = *(uint32_t*)&h0, h1u = *(uint32_t*)&h1;
    uint32_t l0u = *(uint32_t*)&l0, l1u = *(uint32_t*)&l1;
    asm volatile("st.shared.v2.b32 [%0], {%1, %2};" :: "r"(sb + hi_off), "r"(h0u), "r"(h1u) : "memory");
    asm volatile("st.shared.v2.b32 [%0], {%1, %2};" :: "r"(sb + lo_off), "r"(l0u), "r"(l1u) : "memory");
}

__global__ __launch_bounds__(256, 2)
void fcgat_hmma(const float* __restrict__ A,     // x  [32768, 256]
                const float* __restrict__ W,     // W  [256, 256]
                const float* __restrict__ bias,  // [256]
                float* __restrict__ C)           // [32768, 256]
{
    extern __shared__ __align__(16) unsigned char smem[];
    const uint32_t sb = smem_u32(smem);

    const int t   = threadIdx.x;
    const int l   = t & 31;
    const int wid = t >> 5;
    const int wm  = wid & 3;          // 4 warps along M
    const int wn  = wid >> 2;         // 2 warps along N
    const int m0  = wm * 32;
    const int n0  = wn * 32;

    const float* Ag = A + (size_t)blockIdx.y * BM * D_DIM;
    const float* Bg = W + (size_t)blockIdx.x * BN * D_DIM;

    // Per-thread load coordinates (fixed across chunks).
    const int arow0 = t >> 1;                 // with 2 float4/row-pass pattern below
    // A: 128 rows x 8 float4 = 1024 -> 4/thread ; B: 512 -> 2/thread.
    // reuse R4 mapping: idx = t + i*256 ; row = idx>>3 ; c4 = idx&7
    float acc[2][4][4];
    #pragma unroll
    for (int i = 0; i < 2; i++)
        #pragma unroll
        for (int j = 0; j < 4; j++)
            #pragma unroll
            for (int c = 0; c < 4; c++)
                acc[i][j][c] = 0.0f;

    const uint32_t a_lane = (uint32_t)((m0 + (l & 15)) * ROWB + (l >> 4) * 16);
    const uint32_t b_lane = (uint32_t)((n0 + (l & 7) + ((l >> 4) << 3)) * ROWB
                                       + ((l >> 3) & 1) * 16);

    float4 pa[4];
    float4 pb[2];

    // ---- prologue: load + store chunk 0 ----
    #pragma unroll
    for (int i = 0; i < 4; i++) {
        int idx = t + i * 256;
        pa[i] = *(const float4*)(Ag + (size_t)(idx >> 3) * D_DIM + (idx & 7) * 4);
    }
    #pragma unroll
    for (int i = 0; i < 2; i++) {
        int idx = t + i * 256;
        pb[i] = *(const float4*)(Bg + (size_t)(idx >> 3) * D_DIM + (idx & 7) * 4);
    }
    #pragma unroll
    for (int i = 0; i < 4; i++) {
        int idx = t + i * 256;
        uint32_t so = (uint32_t)((idx >> 3) * ROWB + (idx & 7) * 8);
        split_store(sb, OFF_AH + so, OFF_AL + so, pa[i]);
    }
    #pragma unroll
    for (int i = 0; i < 2; i++) {
        int idx = t + i * 256;
        uint32_t so = (uint32_t)((idx >> 3) * ROWB + (idx & 7) * 8);
        split_store(sb, OFF_BH + so, OFF_BL + so, pb[i]);
    }
    __syncthreads();

    uint32_t stage = 0;
    for (int ch = 0; ch < N_CHUNKS; ch++) {
        const bool more = (ch + 1 < N_CHUNKS);
        const int kn = (ch + 1) * BK;

        // (1) issue next chunk's global loads (latency hidden behind MMAs)
        if (more) {
            #pragma unroll
            for (int i = 0; i < 4; i++) {
                int idx = t + i * 256;
                pa[i] = *(const float4*)(Ag + (size_t)(idx >> 3) * D_DIM + kn + (idx & 7) * 4);
            }
            #pragma unroll
            for (int i = 0; i < 2; i++) {
                int idx = t + i * 256;
                pb[i] = *(const float4*)(Bg + (size_t)(idx >> 3) * D_DIM + kn + (idx & 7) * 4);
            }
        }

        // (2) compute current chunk from stage `stage`
        const uint32_t base = sb + stage;
        #pragma unroll
        for (int ks = 0; ks < 2; ks++) {
            const uint32_t ko = (uint32_t)(ks * 32);   // 16 bf16 = 32 B
            uint32_t ah[2][4], al[2][4], bh[2][4], bl[2][4];
            #pragma unroll
            for (int i = 0; i < 2; i++) {
                ldsm_x4(ah[i], base + OFF_AH + a_lane + ko + i * 16 * ROWB);
                ldsm_x4(al[i], base + OFF_AL + a_lane + ko + i * 16 * ROWB);
            }
            #pragma unroll
            for (int jp = 0; jp < 2; jp++) {
                ldsm_x4(bh[jp], base + OFF_BH + b_lane + ko + jp * 16 * ROWB);
                ldsm_x4(bl[jp], base + OFF_BL + b_lane + ko + jp * 16 * ROWB);
            }
            #pragma unroll
            for (int i = 0; i < 2; i++)
                #pragma unroll
                for (int j = 0; j < 4; j++) {
                    const uint32_t* bhf = bh[j >> 1] + (j & 1) * 2;
                    const uint32_t* blf = bl[j >> 1] + (j & 1) * 2;
                    mma_bf16(acc[i][j], ah[i], bhf);   // xh * Wh
                    mma_bf16(acc[i][j], ah[i], blf);   // xh * Wl
                    mma_bf16(acc[i][j], al[i], bhf);   // xl * Wh
                }
        }

        // (3) convert + store next chunk into the other stage
        const uint32_t nbase = sb + (stage ^ STAGE_BYTES);
        if (more) {
            #pragma unroll
            for (int i = 0; i < 4; i++) {
                int idx = t + i * 256;
                uint32_t so = (uint32_t)((idx >> 3) * ROWB + (idx & 7) * 8);
                split_store(nbase, OFF_AH + so, OFF_AL + so, pa[i]);
            }
            #pragma unroll
            for (int i = 0; i < 2; i++) {
                int idx = t + i * 256;
                uint32_t so = (uint32_t)((idx >> 3) * ROWB + (idx & 7) * 8);
                split_store(nbase, OFF_BH + so, OFF_BL + so, pb[i]);
            }
        }

        // (4) single barrier per chunk
        __syncthreads();
        stage ^= STAGE_BYTES;
    }

    // ---- epilogue: bias + relu ----
    const int g  = l >> 2;
    const int tc = l & 3;
    #pragma unroll
    for (int i = 0; i < 2; i++) {
        const size_t r0 = (size_t)blockIdx.y * BM + m0 + 16 * i + g;
        const size_t r1 = r0 + 8;
        #pragma unroll
        for (int j = 0; j < 4; j++) {
            const int col = blockIdx.x * BN + n0 + 8 * j + 2 * tc;
            float2 bv = *(const float2*)(bias + col);
            float2 o0, o1;
            o0.x = fmaxf(acc[i][j][0] + bv.x, 0.0f);
            o0.y = fmaxf(acc[i][j][1] + bv.y, 0.0f);
            o1.x = fmaxf(acc[i][j][2] + bv.x, 0.0f);
            o1.y = fmaxf(acc[i][j][3] + bv.y, 0.0f);
            *(float2*)(C + r0 * D_DIM + col) = o0;
            *(float2*)(C + r1 * D_DIM + col) = o1;
        }
    }
}

extern "C" void kernel_launch(void* const* d_in, const int* in_sizes, int n_in,
                              void* d_out, int out_size)
{
    const float* x   = (const float*)d_in[0];
    const float* W_w = (const float*)d_in[1];
    const float* W_b = (const float*)d_in[2];
    float* out = (float*)d_out;

    int M = in_sizes[0] / D_DIM;                  // 32768
    cudaFuncSetAttribute(fcgat_hmma,
                         cudaFuncAttributeMaxDynamicSharedMemorySize, SMEM_TOTAL);
    dim3 grid(D_DIM / BN, M / BM);                // (4, 256) = 1024 CTAs
    fcgat_hmma<<<grid, 256, SMEM_TOTAL>>>(x, W_w, W_b, out);
}